// round 1
// baseline (speedup 1.0000x reference)
#include <cuda_runtime.h>
#include <math.h>

// ---------------- problem dims ----------------
#define NB    4096
#define NIN   8192
#define NEMB  1024
#define NK    4096
#define NCD   256
#define NFLAT 16384               // NB * 4
#define OUT_PERP_OFF ((size_t)1 + (size_t)NB * (size_t)NIN)

// ---------------- scratch (device globals, no allocation) ----------------
__device__ float g_act[(size_t)NB * NEMB];
__device__ float g_h  [(size_t)NB * NEMB];
__device__ float g_h2 [(size_t)NB * NEMB];
__device__ float g_cnorm[NK];
__device__ int   g_idx[NFLAT];
__device__ int   g_cnt[NK];
__device__ float g_losspart[NFLAT / 8];   // 2048 block partials (deterministic)

// ---------------- tiled fused SGEMM ----------------
#define BM 128
#define BN 64
#define BK 16

#define EPI_BN_RELU 0
#define EPI_BIAS    1
#define EPI_RES     2
#define EPI_SIG     3

template<int EPI, bool RELU_A>
__global__ __launch_bounds__(256)
void gemm_fused(const float* __restrict__ A, const float* __restrict__ W,
                const float* __restrict__ bias,
                const float* __restrict__ gamma, const float* __restrict__ beta,
                const float* __restrict__ mean,  const float* __restrict__ var,
                const float* __restrict__ res,
                float* __restrict__ C, int M, int N, int K)
{
    __shared__ float As[BK][BM];   // 8 KB
    __shared__ float Bs[BK][BN];   // 4 KB

    const int tid      = threadIdx.x;
    const int row_base = blockIdx.y * BM;
    const int col_base = blockIdx.x * BN;

    // A-tile loaders: thread -> (row ar / ar+64, k quad ak)
    const int ar = tid >> 2;              // 0..63
    const int ak = (tid & 3) << 2;        // 0,4,8,12
    // B-tile loaders: thread -> (k row bk, col quad bc)
    const int bk = tid >> 4;              // 0..15
    const int bc = (tid & 15) << 2;       // 0..60

    const float* Aptr  = A + (size_t)(row_base + ar) * K + ak;
    const float* Aptr2 = A + (size_t)(row_base + ar + 64) * K + ak;
    const float* Wptr  = W + (size_t)bk * N + col_base + bc;

    // compute mapping: 16x16 threads, 8 rows x 4 cols each
    const int r0 = (tid >> 4) * 8;
    const int c0 = (tid & 15) * 4;

    float acc[8][4];
#pragma unroll
    for (int i = 0; i < 8; i++)
#pragma unroll
        for (int j = 0; j < 4; j++) acc[i][j] = 0.f;

    for (int k0 = 0; k0 < K; k0 += BK) {
        float4 a0 = *(const float4*)(Aptr  + k0);
        float4 a1 = *(const float4*)(Aptr2 + k0);
        float4 b0 = *(const float4*)(Wptr + (size_t)k0 * N);
        if (RELU_A) {
            a0.x = fmaxf(a0.x, 0.f); a0.y = fmaxf(a0.y, 0.f);
            a0.z = fmaxf(a0.z, 0.f); a0.w = fmaxf(a0.w, 0.f);
            a1.x = fmaxf(a1.x, 0.f); a1.y = fmaxf(a1.y, 0.f);
            a1.z = fmaxf(a1.z, 0.f); a1.w = fmaxf(a1.w, 0.f);
        }
        __syncthreads();
        As[ak + 0][ar]      = a0.x; As[ak + 1][ar]      = a0.y;
        As[ak + 2][ar]      = a0.z; As[ak + 3][ar]      = a0.w;
        As[ak + 0][ar + 64] = a1.x; As[ak + 1][ar + 64] = a1.y;
        As[ak + 2][ar + 64] = a1.z; As[ak + 3][ar + 64] = a1.w;
        *(float4*)&Bs[bk][bc] = b0;
        __syncthreads();

#pragma unroll
        for (int kk = 0; kk < BK; kk++) {
            float4 av0 = *(const float4*)&As[kk][r0];
            float4 av1 = *(const float4*)&As[kk][r0 + 4];
            float4 bv  = *(const float4*)&Bs[kk][c0];
            float a[8] = {av0.x, av0.y, av0.z, av0.w, av1.x, av1.y, av1.z, av1.w};
            float b[4] = {bv.x, bv.y, bv.z, bv.w};
#pragma unroll
            for (int i = 0; i < 8; i++)
#pragma unroll
                for (int j = 0; j < 4; j++)
                    acc[i][j] += a[i] * b[j];
        }
    }

    // ---- epilogue ----
    float bcol[4], gs[4], bt[4], mn[4];
#pragma unroll
    for (int j = 0; j < 4; j++) {
        int c = col_base + c0 + j;
        bcol[j] = bias[c];
        if (EPI == EPI_BN_RELU || EPI == EPI_RES) {
            gs[j] = gamma[c] * rsqrtf(var[c] + 1e-5f);
            bt[j] = beta[c];
            mn[j] = mean[c];
        }
    }

#pragma unroll
    for (int i = 0; i < 8; i++) {
        int r = row_base + r0 + i;
        size_t off = (size_t)r * N + col_base + c0;
        float4 rv;
        if (EPI == EPI_RES) rv = *(const float4*)(res + off);
        float o[4];
#pragma unroll
        for (int j = 0; j < 4; j++) {
            float c = acc[i][j] + bcol[j];
            if (EPI == EPI_BN_RELU) {
                c = (c - mn[j]) * gs[j] + bt[j];
                c = fmaxf(c, 0.f);
            } else if (EPI == EPI_RES) {
                c = (c - mn[j]) * gs[j] + bt[j];
                float rr = (j == 0) ? rv.x : (j == 1) ? rv.y : (j == 2) ? rv.z : rv.w;
                c = rr + c;
            } else if (EPI == EPI_SIG) {
                c = 1.f / (1.f + expf(-c));
            }
            o[j] = c;
        }
        if (EPI == EPI_SIG) {
            // destination (d_out+1) is only 4-byte aligned -> scalar stores
            C[off + 0] = o[0]; C[off + 1] = o[1];
            C[off + 2] = o[2]; C[off + 3] = o[3];
        } else {
            float4 v; v.x = o[0]; v.y = o[1]; v.z = o[2]; v.w = o[3];
            *(float4*)(C + off) = v;
        }
    }
}

// ---------------- helpers ----------------
__global__ void zero_cnt_kernel()
{
    int i = blockIdx.x * 256 + threadIdx.x;
    if (i < NK) g_cnt[i] = 0;
}

__global__ __launch_bounds__(256)
void cnorm_kernel(const float* __restrict__ CB)
{
    int warp = threadIdx.x >> 5, lane = threadIdx.x & 31;
    int code = blockIdx.x * 8 + warp;
    const float* c = CB + (size_t)code * NCD;
    float s = 0.f;
#pragma unroll
    for (int e = 0; e < 8; e++) { float v = c[e * 32 + lane]; s += v * v; }
#pragma unroll
    for (int o = 16; o > 0; o >>= 1) s += __shfl_xor_sync(0xffffffffu, s, o);
    if (lane == 0) g_cnorm[code] = s;
}

// ---------------- VQ: distances + argmin ----------------
// block: 64 rows of flat z, loop over 4096 codes in tiles of 64, fp32 dots.
// d(k) = |cb_k|^2 - 2 z.cb_k   (the |z|^2 shift is order-invariant for argmin)
__global__ __launch_bounds__(256)
void vq_kernel(const float* __restrict__ Z, const float* __restrict__ CB)
{
    __shared__ float Zs[64][64];     // 16 KB  (k-major, transposed)
    __shared__ float Bs[64][64];     // 16 KB
    __shared__ float sv[64][16];     //  4 KB
    __shared__ int   si[64][16];     //  4 KB

    const int tid = threadIdx.x;
    const int rb  = blockIdx.x * 64;
    const int lr  = tid >> 2;            // 0..63
    const int lk  = (tid & 3) << 2;      // 0,4,8,12
    const int r0  = (tid >> 4) * 4;
    const int c0  = (tid & 15) * 4;

    float minv[4]; int mini[4];
#pragma unroll
    for (int i = 0; i < 4; i++) { minv[i] = 3.4e38f; mini[i] = 0; }

    for (int ct = 0; ct < NK; ct += 64) {
        float acc[4][4];
#pragma unroll
        for (int i = 0; i < 4; i++)
#pragma unroll
            for (int j = 0; j < 4; j++) acc[i][j] = 0.f;

        for (int kc = 0; kc < NCD; kc += 64) {
            float4 za[4], ba[4];
#pragma unroll
            for (int p = 0; p < 4; p++) {
                za[p] = *(const float4*)(Z  + (size_t)(rb + lr) * NCD + kc + p * 16 + lk);
                ba[p] = *(const float4*)(CB + (size_t)(ct + lr) * NCD + kc + p * 16 + lk);
            }
            __syncthreads();
#pragma unroll
            for (int p = 0; p < 4; p++) {
                int kb = p * 16 + lk;
                Zs[kb + 0][lr] = za[p].x; Zs[kb + 1][lr] = za[p].y;
                Zs[kb + 2][lr] = za[p].z; Zs[kb + 3][lr] = za[p].w;
                Bs[kb + 0][lr] = ba[p].x; Bs[kb + 1][lr] = ba[p].y;
                Bs[kb + 2][lr] = ba[p].z; Bs[kb + 3][lr] = ba[p].w;
            }
            __syncthreads();

#pragma unroll 16
            for (int kk = 0; kk < 64; kk++) {
                float4 a = *(const float4*)&Zs[kk][r0];
                float4 b = *(const float4*)&Bs[kk][c0];
                float av[4] = {a.x, a.y, a.z, a.w};
                float bv[4] = {b.x, b.y, b.z, b.w};
#pragma unroll
                for (int i = 0; i < 4; i++)
#pragma unroll
                    for (int j = 0; j < 4; j++)
                        acc[i][j] += av[i] * bv[j];
            }
        }

#pragma unroll
        for (int j = 0; j < 4; j++) {
            int k = ct + c0 + j;
            float cn = g_cnorm[k];
#pragma unroll
            for (int i = 0; i < 4; i++) {
                float d = cn - 2.f * acc[i][j];
                if (d < minv[i]) { minv[i] = d; mini[i] = k; }
            }
        }
    }

    __syncthreads();
#pragma unroll
    for (int i = 0; i < 4; i++) { sv[r0 + i][c0 >> 2] = minv[i]; si[r0 + i][c0 >> 2] = mini[i]; }
    __syncthreads();
    if (tid < 64) {
        float bv = sv[tid][0]; int bi = si[tid][0];
#pragma unroll
        for (int t = 1; t < 16; t++) {
            float v = sv[tid][t]; int k2 = si[tid][t];
            if (v < bv || (v == bv && k2 < bi)) { bv = v; bi = k2; }
        }
        g_idx[rb + tid] = bi;
        atomicAdd(&g_cnt[bi], 1);
    }
}

// ---------------- gather quantized + loss partials ----------------
__global__ __launch_bounds__(256)
void gather_loss_kernel(const float* __restrict__ Z, const float* __restrict__ CB,
                        float* __restrict__ HQ)
{
    __shared__ float ws[8];
    int warp = threadIdx.x >> 5, lane = threadIdx.x & 31;
    int row  = blockIdx.x * 8 + warp;
    int id   = g_idx[row];
    const float* q = CB + (size_t)id * NCD;
    const float* z = Z + (size_t)row * NCD;
    float* o       = HQ + (size_t)row * NCD;
    float s = 0.f;
#pragma unroll
    for (int e = 0; e < 8; e++) {
        int d = e * 32 + lane;
        float qq = q[d], zz = z[d];
        o[d] = qq;
        float t = qq - zz;
        s += t * t;
    }
#pragma unroll
    for (int off = 16; off > 0; off >>= 1) s += __shfl_xor_sync(0xffffffffu, s, off);
    if (lane == 0) ws[warp] = s;
    __syncthreads();
    if (threadIdx.x == 0) {
        float t = 0.f;
#pragma unroll
        for (int w = 0; w < 8; w++) t += ws[w];
        g_losspart[blockIdx.x] = t;
    }
}

// ---------------- finalize loss + perplexity ----------------
__global__ __launch_bounds__(256)
void finalize_kernel(float* __restrict__ out)
{
    __shared__ float red[256];
    int tid = threadIdx.x;

    float s = 0.f;
    for (int i = tid; i < NFLAT / 8; i += 256) s += g_losspart[i];
    red[tid] = s; __syncthreads();
    for (int o = 128; o > 0; o >>= 1) { if (tid < o) red[tid] += red[tid + o]; __syncthreads(); }
    float loss = red[0] * (1.25f / ((float)NB * (float)NEMB));
    __syncthreads();

    float e = 0.f;
    for (int i = tid; i < NK; i += 256) {
        float p = (float)g_cnt[i] * (1.0f / (float)NFLAT);
        e += p * logf(p + 1e-10f);
    }
    red[tid] = e; __syncthreads();
    for (int o = 128; o > 0; o >>= 1) { if (tid < o) red[tid] += red[tid + o]; __syncthreads(); }

    if (tid == 0) {
        out[0]            = loss;
        out[OUT_PERP_OFF] = expf(-red[0]);
    }
}

// ---------------- launch ----------------
extern "C" void kernel_launch(void* const* d_in, const int* in_sizes, int n_in,
                              void* d_out, int out_size)
{
    const float* x    = (const float*)d_in[0];
    const float* W1   = (const float*)d_in[1];
    const float* b1   = (const float*)d_in[2];
    const float* bn1g = (const float*)d_in[3];
    const float* bn1b = (const float*)d_in[4];
    const float* bn1m = (const float*)d_in[5];
    const float* bn1v = (const float*)d_in[6];
    const float* W2   = (const float*)d_in[7];
    const float* b2   = (const float*)d_in[8];
    const float* rbW  = (const float*)d_in[9];
    const float* rbb  = (const float*)d_in[10];
    const float* rbg  = (const float*)d_in[11];
    const float* rbbe = (const float*)d_in[12];
    const float* rbm  = (const float*)d_in[13];
    const float* rbv  = (const float*)d_in[14];
    const float* cb   = (const float*)d_in[15];
    const float* decW = (const float*)d_in[16];
    const float* decb = (const float*)d_in[17];
    float* out = (float*)d_out;

    float *act, *h, *h2;
    cudaGetSymbolAddress((void**)&act, g_act);
    cudaGetSymbolAddress((void**)&h,   g_h);
    cudaGetSymbolAddress((void**)&h2,  g_h2);

    const size_t WS = (size_t)NEMB * NEMB;
    dim3 blk(256);
    dim3 gEmb(NEMB / BN, NB / BM);     // 16 x 32
    dim3 gDec(NIN  / BN, NB / BM);     // 128 x 32

    zero_cnt_kernel<<<(NK + 255) / 256, 256>>>();
    cnorm_kernel<<<NK / 8, 256>>>(cb);

    // encoder
    gemm_fused<EPI_BN_RELU, false><<<gEmb, blk>>>(x, W1, b1, bn1g, bn1b, bn1m, bn1v,
                                                  nullptr, act, NB, NEMB, NIN);
    gemm_fused<EPI_BIAS, false><<<gEmb, blk>>>(act, W2, b2, nullptr, nullptr, nullptr, nullptr,
                                               nullptr, h, NB, NEMB, NEMB);
    gemm_fused<EPI_RES, true><<<gEmb, blk>>>(h, rbW + 0 * WS, rbb + 0 * NEMB,
                                             rbg + 0 * NEMB, rbbe + 0 * NEMB,
                                             rbm + 0 * NEMB, rbv + 0 * NEMB,
                                             h, h2, NB, NEMB, NEMB);
    gemm_fused<EPI_RES, true><<<gEmb, blk>>>(h2, rbW + 1 * WS, rbb + 1 * NEMB,
                                             rbg + 1 * NEMB, rbbe + 1 * NEMB,
                                             rbm + 1 * NEMB, rbv + 1 * NEMB,
                                             h2, h, NB, NEMB, NEMB);

    // vector quantizer (z lives in h)
    vq_kernel<<<NFLAT / 64, 256>>>(h, cb);
    gather_loss_kernel<<<NFLAT / 8, 256>>>(h, cb, act);   // hq -> act
    finalize_kernel<<<1, 256>>>(out);

    // decoder resblocks 2,3,4
    gemm_fused<EPI_RES, true><<<gEmb, blk>>>(act, rbW + 2 * WS, rbb + 2 * NEMB,
                                             rbg + 2 * NEMB, rbbe + 2 * NEMB,
                                             rbm + 2 * NEMB, rbv + 2 * NEMB,
                                             act, h2, NB, NEMB, NEMB);
    gemm_fused<EPI_RES, true><<<gEmb, blk>>>(h2, rbW + 3 * WS, rbb + 3 * NEMB,
                                             rbg + 3 * NEMB, rbbe + 3 * NEMB,
                                             rbm + 3 * NEMB, rbv + 3 * NEMB,
                                             h2, h, NB, NEMB, NEMB);
    gemm_fused<EPI_RES, true><<<gEmb, blk>>>(h, rbW + 4 * WS, rbb + 4 * NEMB,
                                             rbg + 4 * NEMB, rbbe + 4 * NEMB,
                                             rbm + 4 * NEMB, rbv + 4 * NEMB,
                                             h, h2, NB, NEMB, NEMB);

    // final projection + sigmoid -> x_recon at out+1 (scalar stores, unaligned base)
    gemm_fused<EPI_SIG, false><<<gDec, blk>>>(h2, decW, decb, nullptr, nullptr, nullptr, nullptr,
                                              nullptr, out + 1, NB, NIN, NEMB);
}

// round 2
// speedup vs baseline: 3.8461x; 3.8461x over previous
#include <cuda_runtime.h>
#include <math.h>
#include <stdint.h>

// ---------------- problem dims ----------------
#define NB    4096
#define NIN   8192
#define NEMB  1024
#define NK    4096
#define NCD   256
#define NFLAT 16384
#define OUT_PERP_OFF ((size_t)1 + (size_t)NB * (size_t)NIN)

#define EPI_BN_RELU 0
#define EPI_BIAS    1
#define EPI_RES     2
#define EPI_SIG     3

// ---------------- scratch (device globals) ----------------
__device__ float g_xr  [(size_t)NB * NIN];
__device__ float g_w1r [(size_t)NIN * NEMB];
__device__ float g_w2r [(size_t)NEMB * NEMB];
__device__ float g_rbwr[(size_t)5 * NEMB * NEMB];
__device__ float g_decwr[(size_t)NEMB * NIN];
__device__ float g_cbr [(size_t)NK * NCD];
__device__ float g_a   [(size_t)NB * NEMB];
__device__ float g_ar  [(size_t)NB * NEMB];
__device__ float g_b   [(size_t)NB * NEMB];
__device__ float g_br  [(size_t)NB * NEMB];
__device__ float g_z   [(size_t)NB * NEMB];
__device__ float g_cnorm[NK];
__device__ int   g_idx[NFLAT];
__device__ int   g_cnt[NK];
__device__ float g_losspart[NFLAT / 8];

// ---------------- small helpers ----------------
__device__ __forceinline__ uint32_t rtf32_u(float x) {
    uint32_t r;
    asm("cvt.rna.tf32.f32 %0, %1;" : "=r"(r) : "f"(x));
    return r;
}
__device__ __forceinline__ float rtf32(float x) {
    return __uint_as_float(rtf32_u(x));
}
__device__ __forceinline__ void cp16(uint32_t dst, const void* src) {
    asm volatile("cp.async.cg.shared.global [%0], [%1], 16;" :: "r"(dst), "l"(src));
}
__device__ __forceinline__ void cp_commit() {
    asm volatile("cp.async.commit_group;");
}
template<int N>
__device__ __forceinline__ void cp_wait() {
    asm volatile("cp.async.wait_group %0;" :: "n"(N));
}
__device__ __forceinline__ void mma8(float* c, const uint32_t* a, const uint32_t* b) {
    asm volatile(
        "mma.sync.aligned.m16n8k8.row.col.f32.tf32.tf32.f32 "
        "{%0,%1,%2,%3},{%4,%5,%6,%7},{%8,%9},{%0,%1,%2,%3};"
        : "+f"(c[0]), "+f"(c[1]), "+f"(c[2]), "+f"(c[3])
        : "r"(a[0]), "r"(a[1]), "r"(a[2]), "r"(a[3]), "r"(b[0]), "r"(b[1]));
}

// ---------------- tf32 tensor-core GEMM ----------------
// block tile 128x256, BK=32, 8 warps (2x4), warp tile 64x64, m16n8k8.
#define TBM 128
#define TBN 256
#define TBK 32
#define A_STR 36                         // BK + 4 pad (floats)
#define AS_SZ (TBM * A_STR)              // 4608 floats / stage
#define BS_SZ (TBK * TBN)                // 8192 floats / stage
#define GEMM_SMEM ((2 * AS_SZ + 2 * BS_SZ) * 4)

template<int EPI, bool WRELU>
__global__ void __launch_bounds__(256, 1)
gemm_tc(const float* __restrict__ A, const float* __restrict__ W,
        const float* __restrict__ bias,
        const float* __restrict__ gamma, const float* __restrict__ beta,
        const float* __restrict__ mean,  const float* __restrict__ var,
        const float* __restrict__ res,
        float* __restrict__ out0, float* __restrict__ out1,
        int M, int N, int K)
{
    extern __shared__ float smem[];
    float* As = smem;                    // 2 stages
    float* Bs = smem + 2 * AS_SZ;
    const uint32_t s_as = (uint32_t)__cvta_generic_to_shared(As);
    const uint32_t s_bs = (uint32_t)__cvta_generic_to_shared(Bs);

    const int tid  = threadIdx.x;
    const int lane = tid & 31;
    const int warp = tid >> 5;
    const int wm   = warp >> 2;          // 0..1
    const int wn   = warp & 3;           // 0..3
    const int row0 = blockIdx.y * TBM;
    const int col0 = blockIdx.x * TBN;
    const int l4   = lane >> 2;          // group id 0..7
    const int lm   = lane & 3;           // 0..3

    float acc[4][8][4];
#pragma unroll
    for (int mt = 0; mt < 4; mt++)
#pragma unroll
        for (int nt = 0; nt < 8; nt++)
#pragma unroll
            for (int q = 0; q < 4; q++) acc[mt][nt][q] = 0.f;

    const int iters = K / TBK;

    auto loadA = [&](int s, int k0) {
#pragma unroll
        for (int i = 0; i < 4; i++) {
            int idx = i * 256 + tid;
            int r = idx >> 3, kc = (idx & 7) << 2;
            cp16(s_as + (uint32_t)(s * AS_SZ + r * A_STR + kc) * 4,
                 A + (size_t)(row0 + r) * K + k0 + kc);
        }
    };
    auto loadB = [&](int s, int k0) {
#pragma unroll
        for (int i = 0; i < 8; i++) {
            int idx = i * 256 + tid;
            int k = idx >> 6, nc = (idx & 63) << 2;
            int nsw = nc ^ ((k & 3) << 3);
            cp16(s_bs + (uint32_t)(s * BS_SZ + k * TBN + nsw) * 4,
                 W + (size_t)(k0 + k) * N + col0 + nc);
        }
    };

    loadA(0, 0); loadB(0, 0); cp_commit();

    int s = 0;
    for (int it = 0; it < iters; it++) {
        if (it + 1 < iters) {
            loadA(s ^ 1, (it + 1) * TBK);
            loadB(s ^ 1, (it + 1) * TBK);
            cp_commit();
            cp_wait<1>();
        } else {
            cp_wait<0>();
        }
        __syncthreads();

        const float* as = As + s * AS_SZ;
        const float* bs = Bs + s * BS_SZ;
#pragma unroll
        for (int kk = 0; kk < TBK; kk += 8) {
            uint32_t af[4][4], bf[8][2];
#pragma unroll
            for (int mt = 0; mt < 4; mt++) {
                int r = wm * 64 + mt * 16 + l4;
                af[mt][0] = __float_as_uint(as[r * A_STR + kk + lm]);
                af[mt][1] = __float_as_uint(as[(r + 8) * A_STR + kk + lm]);
                af[mt][2] = __float_as_uint(as[r * A_STR + kk + 4 + lm]);
                af[mt][3] = __float_as_uint(as[(r + 8) * A_STR + kk + 4 + lm]);
            }
#pragma unroll
            for (int nt = 0; nt < 8; nt++) {
                int c   = wn * 64 + nt * 8 + l4;
                int csw = c ^ (lm << 3);
                bf[nt][0] = __float_as_uint(bs[(kk + lm) * TBN + csw]);
                bf[nt][1] = __float_as_uint(bs[(kk + 4 + lm) * TBN + csw]);
            }
#pragma unroll
            for (int mt = 0; mt < 4; mt++)
#pragma unroll
                for (int nt = 0; nt < 8; nt++)
                    mma8(acc[mt][nt], af[mt], bf[nt]);
        }
        __syncthreads();
        s ^= 1;
    }

    // ---- epilogue ----
#pragma unroll
    for (int nt = 0; nt < 8; nt++) {
        int c = col0 + wn * 64 + nt * 8 + (lm << 1);
        float b0 = bias[c], b1 = bias[c + 1];
        float g0 = 0.f, g1 = 0.f, be0 = 0.f, be1 = 0.f, m0 = 0.f, m1 = 0.f;
        if (EPI == EPI_BN_RELU || EPI == EPI_RES) {
            g0 = gamma[c]     * rsqrtf(var[c]     + 1e-5f);
            g1 = gamma[c + 1] * rsqrtf(var[c + 1] + 1e-5f);
            be0 = beta[c]; be1 = beta[c + 1];
            m0 = mean[c]; m1 = mean[c + 1];
        }
#pragma unroll
        for (int mt = 0; mt < 4; mt++) {
#pragma unroll
            for (int h = 0; h < 2; h++) {
                int r = row0 + wm * 64 + mt * 16 + l4 + h * 8;
                size_t off = (size_t)r * N + c;
                float x0 = acc[mt][nt][h * 2 + 0] + b0;
                float x1 = acc[mt][nt][h * 2 + 1] + b1;
                if (EPI == EPI_BN_RELU) {
                    x0 = fmaxf((x0 - m0) * g0 + be0, 0.f);
                    x1 = fmaxf((x1 - m1) * g1 + be1, 0.f);
                } else if (EPI == EPI_RES) {
                    float2 rv = *(const float2*)(res + off);
                    x0 = (x0 - m0) * g0 + be0 + rv.x;
                    x1 = (x1 - m1) * g1 + be1 + rv.y;
                } else if (EPI == EPI_SIG) {
                    // final output: full fp32, scalar stores (base unaligned)
                    out0[off]     = 1.f / (1.f + expf(-x0));
                    out0[off + 1] = 1.f / (1.f + expf(-x1));
                    continue;
                }
                float r0 = rtf32(x0), r1 = rtf32(x1);
                float2 v; v.x = r0; v.y = r1;
                *(float2*)(out0 + off) = v;
                if (WRELU) {
                    float2 w; w.x = fmaxf(r0, 0.f); w.y = fmaxf(r1, 0.f);
                    *(float2*)(out1 + off) = w;
                }
            }
        }
    }
}

// ---------------- VQ: tf32 mma distances + fused argmin ----------------
// block: 128 rows x (loop over 4096 codes in tiles of 256), K=256.
#define VB_STR 36
#define VBS_SZ (256 * VB_STR)
#define VQ_SMEM ((2 * AS_SZ + 2 * VBS_SZ) * 4)

__global__ void __launch_bounds__(256, 1)
vq_tc(const float* __restrict__ Z, const float* __restrict__ CB)
{
    extern __shared__ float smem[];
    float* As = smem;
    float* Bs = smem + 2 * AS_SZ;
    const uint32_t s_as = (uint32_t)__cvta_generic_to_shared(As);
    const uint32_t s_bs = (uint32_t)__cvta_generic_to_shared(Bs);
    __shared__ float sv[128][4];
    __shared__ int   si[128][4];

    const int tid  = threadIdx.x;
    const int lane = tid & 31;
    const int warp = tid >> 5;
    const int wm   = warp >> 2;
    const int wn   = warp & 3;
    const int row0 = blockIdx.x * 128;
    const int l4   = lane >> 2;
    const int lm   = lane & 3;

    float minv[4][2];
    int   mini[4][2];
#pragma unroll
    for (int mt = 0; mt < 4; mt++)
#pragma unroll
        for (int h = 0; h < 2; h++) { minv[mt][h] = 3.4e38f; mini[mt][h] = 0; }

    auto loadA = [&](int s, int k0) {
#pragma unroll
        for (int i = 0; i < 4; i++) {
            int idx = i * 256 + tid;
            int r = idx >> 3, kc = (idx & 7) << 2;
            cp16(s_as + (uint32_t)(s * AS_SZ + r * A_STR + kc) * 4,
                 Z + (size_t)(row0 + r) * NCD + k0 + kc);
        }
    };

    for (int ct = 0; ct < NK; ct += 256) {
        float acc[4][8][4];
#pragma unroll
        for (int mt = 0; mt < 4; mt++)
#pragma unroll
            for (int nt = 0; nt < 8; nt++)
#pragma unroll
                for (int q = 0; q < 4; q++) acc[mt][nt][q] = 0.f;

        auto loadB = [&](int s, int k0) {
#pragma unroll
            for (int i = 0; i < 8; i++) {
                int idx = i * 256 + tid;
                int code = idx >> 3, kc = (idx & 7) << 2;
                cp16(s_bs + (uint32_t)(s * VBS_SZ + code * VB_STR + kc) * 4,
                     CB + (size_t)(ct + code) * NCD + k0 + kc);
            }
        };

        loadA(0, 0); loadB(0, 0); cp_commit();
        int s = 0;
        const int iters = NCD / TBK;      // 8
        for (int it = 0; it < iters; it++) {
            if (it + 1 < iters) {
                loadA(s ^ 1, (it + 1) * TBK);
                loadB(s ^ 1, (it + 1) * TBK);
                cp_commit();
                cp_wait<1>();
            } else {
                cp_wait<0>();
            }
            __syncthreads();

            const float* as = As + s * AS_SZ;
            const float* bs = Bs + s * VBS_SZ;
#pragma unroll
            for (int kk = 0; kk < TBK; kk += 8) {
                uint32_t af[4][4], bf[8][2];
#pragma unroll
                for (int mt = 0; mt < 4; mt++) {
                    int r = wm * 64 + mt * 16 + l4;
                    af[mt][0] = __float_as_uint(as[r * A_STR + kk + lm]);
                    af[mt][1] = __float_as_uint(as[(r + 8) * A_STR + kk + lm]);
                    af[mt][2] = __float_as_uint(as[r * A_STR + kk + 4 + lm]);
                    af[mt][3] = __float_as_uint(as[(r + 8) * A_STR + kk + 4 + lm]);
                }
#pragma unroll
                for (int nt = 0; nt < 8; nt++) {
                    int cc = wn * 64 + nt * 8 + l4;
                    bf[nt][0] = __float_as_uint(bs[cc * VB_STR + kk + lm]);
                    bf[nt][1] = __float_as_uint(bs[cc * VB_STR + kk + 4 + lm]);
                }
#pragma unroll
                for (int mt = 0; mt < 4; mt++)
#pragma unroll
                    for (int nt = 0; nt < 8; nt++)
                        mma8(acc[mt][nt], af[mt], bf[nt]);
            }
            __syncthreads();
            s ^= 1;
        }

        // update running per-row argmin:  d = |c|^2 - 2 z.c
#pragma unroll
        for (int nt = 0; nt < 8; nt++) {
            int code = ct + wn * 64 + nt * 8 + (lm << 1);
            float cn0 = g_cnorm[code], cn1 = g_cnorm[code + 1];
#pragma unroll
            for (int mt = 0; mt < 4; mt++)
#pragma unroll
                for (int h = 0; h < 2; h++) {
                    float d0 = cn0 - 2.f * acc[mt][nt][h * 2 + 0];
                    float d1 = cn1 - 2.f * acc[mt][nt][h * 2 + 1];
                    if (d0 < minv[mt][h]) { minv[mt][h] = d0; mini[mt][h] = code; }
                    if (d1 < minv[mt][h]) { minv[mt][h] = d1; mini[mt][h] = code + 1; }
                }
        }
    }

    // reduce across the 4 lanes of each quad (they share rows, hold diff cols)
#pragma unroll
    for (int mt = 0; mt < 4; mt++)
#pragma unroll
        for (int h = 0; h < 2; h++) {
            float v = minv[mt][h]; int ix = mini[mt][h];
#pragma unroll
            for (int o = 1; o <= 2; o <<= 1) {
                float vo = __shfl_xor_sync(0xffffffffu, v, o);
                int   io = __shfl_xor_sync(0xffffffffu, ix, o);
                if (vo < v || (vo == v && io < ix)) { v = vo; ix = io; }
            }
            if (lm == 0) {
                int rl = wm * 64 + mt * 16 + l4 + h * 8;
                sv[rl][wn] = v; si[rl][wn] = ix;
            }
        }
    __syncthreads();
    if (tid < 128) {
        float bv = sv[tid][0]; int bi = si[tid][0];
#pragma unroll
        for (int t = 1; t < 4; t++) {
            float v = sv[tid][t]; int k2 = si[tid][t];
            if (v < bv || (v == bv && k2 < bi)) { bv = v; bi = k2; }
        }
        g_idx[row0 + tid] = bi;
        atomicAdd(&g_cnt[bi], 1);
    }
}

// ---------------- misc kernels ----------------
__global__ void round_k(const float* __restrict__ in, float* __restrict__ out, int n4)
{
    int i = blockIdx.x * 256 + threadIdx.x;
    if (i < n4) {
        float4 v = ((const float4*)in)[i];
        v.x = rtf32(v.x); v.y = rtf32(v.y); v.z = rtf32(v.z); v.w = rtf32(v.w);
        ((float4*)out)[i] = v;
    }
}

__global__ void zero_cnt_kernel()
{
    int i = blockIdx.x * 256 + threadIdx.x;
    if (i < NK) g_cnt[i] = 0;
}

__global__ __launch_bounds__(256)
void cnorm_kernel(const float* __restrict__ CB)
{
    int warp = threadIdx.x >> 5, lane = threadIdx.x & 31;
    int code = blockIdx.x * 8 + warp;
    const float* c = CB + (size_t)code * NCD;
    float s = 0.f;
#pragma unroll
    for (int e = 0; e < 8; e++) { float v = c[e * 32 + lane]; s += v * v; }
#pragma unroll
    for (int o = 16; o > 0; o >>= 1) s += __shfl_xor_sync(0xffffffffu, s, o);
    if (lane == 0) g_cnorm[code] = s;
}

__global__ __launch_bounds__(256)
void gather_loss_kernel(const float* __restrict__ Z, const float* __restrict__ CB,
                        float* __restrict__ HQ, float* __restrict__ HQR)
{
    __shared__ float ws[8];
    int warp = threadIdx.x >> 5, lane = threadIdx.x & 31;
    int row  = blockIdx.x * 8 + warp;
    int id   = g_idx[row];
    const float* q = CB + (size_t)id * NCD;
    const float* z = Z + (size_t)row * NCD;
    float* o  = HQ  + (size_t)row * NCD;
    float* orl = HQR + (size_t)row * NCD;
    float s = 0.f;
#pragma unroll
    for (int e = 0; e < 8; e++) {
        int d = e * 32 + lane;
        float qq = q[d], zz = z[d];
        float qr = rtf32(qq);
        o[d]   = qr;
        orl[d] = fmaxf(qr, 0.f);
        float t = qq - zz;
        s += t * t;
    }
#pragma unroll
    for (int off = 16; off > 0; off >>= 1) s += __shfl_xor_sync(0xffffffffu, s, off);
    if (lane == 0) ws[warp] = s;
    __syncthreads();
    if (threadIdx.x == 0) {
        float t = 0.f;
#pragma unroll
        for (int w = 0; w < 8; w++) t += ws[w];
        g_losspart[blockIdx.x] = t;
    }
}

__global__ __launch_bounds__(256)
void finalize_kernel(float* __restrict__ out)
{
    __shared__ float red[256];
    int tid = threadIdx.x;

    float s = 0.f;
    for (int i = tid; i < NFLAT / 8; i += 256) s += g_losspart[i];
    red[tid] = s; __syncthreads();
    for (int o = 128; o > 0; o >>= 1) { if (tid < o) red[tid] += red[tid + o]; __syncthreads(); }
    float loss = red[0] * (1.25f / ((float)NB * (float)NEMB));
    __syncthreads();

    float e = 0.f;
    for (int i = tid; i < NK; i += 256) {
        float p = (float)g_cnt[i] * (1.0f / (float)NFLAT);
        e += p * logf(p + 1e-10f);
    }
    red[tid] = e; __syncthreads();
    for (int o = 128; o > 0; o >>= 1) { if (tid < o) red[tid] += red[tid + o]; __syncthreads(); }

    if (tid == 0) {
        out[0]            = loss;
        out[OUT_PERP_OFF] = expf(-red[0]);
    }
}

// ---------------- launch ----------------
static void round_launch(const float* src, float* dst, size_t n)
{
    int n4 = (int)(n / 4);
    round_k<<<(n4 + 255) / 256, 256>>>(src, dst, n4);
}

extern "C" void kernel_launch(void* const* d_in, const int* in_sizes, int n_in,
                              void* d_out, int out_size)
{
    const float* x    = (const float*)d_in[0];
    const float* W1   = (const float*)d_in[1];
    const float* b1   = (const float*)d_in[2];
    const float* bn1g = (const float*)d_in[3];
    const float* bn1b = (const float*)d_in[4];
    const float* bn1m = (const float*)d_in[5];
    const float* bn1v = (const float*)d_in[6];
    const float* W2   = (const float*)d_in[7];
    const float* b2   = (const float*)d_in[8];
    const float* rbW  = (const float*)d_in[9];
    const float* rbb  = (const float*)d_in[10];
    const float* rbg  = (const float*)d_in[11];
    const float* rbbe = (const float*)d_in[12];
    const float* rbm  = (const float*)d_in[13];
    const float* rbv  = (const float*)d_in[14];
    const float* cb   = (const float*)d_in[15];
    const float* decW = (const float*)d_in[16];
    const float* decb = (const float*)d_in[17];
    float* out = (float*)d_out;

    float *xr, *w1r, *w2r, *rbwr, *decwr, *cbr, *ga, *gar, *gb, *gbr, *gz;
    cudaGetSymbolAddress((void**)&xr,    g_xr);
    cudaGetSymbolAddress((void**)&w1r,   g_w1r);
    cudaGetSymbolAddress((void**)&w2r,   g_w2r);
    cudaGetSymbolAddress((void**)&rbwr,  g_rbwr);
    cudaGetSymbolAddress((void**)&decwr, g_decwr);
    cudaGetSymbolAddress((void**)&cbr,   g_cbr);
    cudaGetSymbolAddress((void**)&ga,    g_a);
    cudaGetSymbolAddress((void**)&gar,   g_ar);
    cudaGetSymbolAddress((void**)&gb,    g_b);
    cudaGetSymbolAddress((void**)&gbr,   g_br);
    cudaGetSymbolAddress((void**)&gz,    g_z);

    // dynamic smem opt-in (idempotent)
    cudaFuncSetAttribute(gemm_tc<EPI_BN_RELU, false>, cudaFuncAttributeMaxDynamicSharedMemorySize, GEMM_SMEM);
    cudaFuncSetAttribute(gemm_tc<EPI_BIAS,    true >, cudaFuncAttributeMaxDynamicSharedMemorySize, GEMM_SMEM);
    cudaFuncSetAttribute(gemm_tc<EPI_RES,     true >, cudaFuncAttributeMaxDynamicSharedMemorySize, GEMM_SMEM);
    cudaFuncSetAttribute(gemm_tc<EPI_RES,     false>, cudaFuncAttributeMaxDynamicSharedMemorySize, GEMM_SMEM);
    cudaFuncSetAttribute(gemm_tc<EPI_SIG,     false>, cudaFuncAttributeMaxDynamicSharedMemorySize, GEMM_SMEM);
    cudaFuncSetAttribute(vq_tc, cudaFuncAttributeMaxDynamicSharedMemorySize, VQ_SMEM);

    const size_t WS = (size_t)NEMB * NEMB;

    // tf32 rounding pre-pass (operands of every MMA)
    round_launch(x,    xr,    (size_t)NB * NIN);
    round_launch(W1,   w1r,   (size_t)NIN * NEMB);
    round_launch(W2,   w2r,   WS);
    round_launch(rbW,  rbwr,  5 * WS);
    round_launch(decW, decwr, (size_t)NEMB * NIN);
    round_launch(cb,   cbr,   (size_t)NK * NCD);

    zero_cnt_kernel<<<(NK + 255) / 256, 256>>>();
    cnorm_kernel<<<NK / 8, 256>>>(cbr);

    dim3 blk(256);
    dim3 gE(NEMB / TBN, NB / TBM);   // 4 x 32
    dim3 gD(NIN  / TBN, NB / TBM);   // 32 x 32

    // encoder
    gemm_tc<EPI_BN_RELU, false><<<gE, blk, GEMM_SMEM>>>(
        xr, w1r, b1, bn1g, bn1b, bn1m, bn1v, nullptr, gar, nullptr, NB, NEMB, NIN);
    gemm_tc<EPI_BIAS, true><<<gE, blk, GEMM_SMEM>>>(
        gar, w2r, b2, nullptr, nullptr, nullptr, nullptr, nullptr, gb, gbr, NB, NEMB, NEMB);
    gemm_tc<EPI_RES, true><<<gE, blk, GEMM_SMEM>>>(
        gbr, rbwr + 0 * WS, rbb + 0 * NEMB, rbg + 0 * NEMB, rbbe + 0 * NEMB,
        rbm + 0 * NEMB, rbv + 0 * NEMB, gb, ga, gar, NB, NEMB, NEMB);
    gemm_tc<EPI_RES, false><<<gE, blk, GEMM_SMEM>>>(
        gar, rbwr + 1 * WS, rbb + 1 * NEMB, rbg + 1 * NEMB, rbbe + 1 * NEMB,
        rbm + 1 * NEMB, rbv + 1 * NEMB, ga, gz, nullptr, NB, NEMB, NEMB);

    // vector quantizer
    vq_tc<<<NFLAT / 128, blk, VQ_SMEM>>>(gz, cbr);
    gather_loss_kernel<<<NFLAT / 8, 256>>>(gz, cb, gb, gbr);
    finalize_kernel<<<1, 256>>>(out);

    // decoder
    gemm_tc<EPI_RES, true><<<gE, blk, GEMM_SMEM>>>(
        gbr, rbwr + 2 * WS, rbb + 2 * NEMB, rbg + 2 * NEMB, rbbe + 2 * NEMB,
        rbm + 2 * NEMB, rbv + 2 * NEMB, gb, ga, gar, NB, NEMB, NEMB);
    gemm_tc<EPI_RES, true><<<gE, blk, GEMM_SMEM>>>(
        gar, rbwr + 3 * WS, rbb + 3 * NEMB, rbg + 3 * NEMB, rbbe + 3 * NEMB,
        rbm + 3 * NEMB, rbv + 3 * NEMB, ga, gb, gbr, NB, NEMB, NEMB);
    gemm_tc<EPI_RES, false><<<gE, blk, GEMM_SMEM>>>(
        gbr, rbwr + 4 * WS, rbb + 4 * NEMB, rbg + 4 * NEMB, rbbe + 4 * NEMB,
        rbm + 4 * NEMB, rbv + 4 * NEMB, gb, ga, nullptr, NB, NEMB, NEMB);

    gemm_tc<EPI_SIG, false><<<gD, blk, GEMM_SMEM>>>(
        ga, decwr, decb, nullptr, nullptr, nullptr, nullptr, nullptr,
        out + 1, nullptr, NB, NIN, NEMB);
}

// round 3
// speedup vs baseline: 3.9002x; 1.0141x over previous
#include <cuda_runtime.h>
#include <math.h>
#include <stdint.h>

// ---------------- problem dims ----------------
#define NB    4096
#define NIN   8192
#define NEMB  1024
#define NK    4096
#define NCD   256
#define NFLAT 16384
#define OUT_PERP_OFF ((size_t)1 + (size_t)NB * (size_t)NIN)

#define EPI_BN_RELU 0
#define EPI_BIAS    1
#define EPI_RES     2
#define EPI_SIG     3

// ---------------- scratch (device globals) ----------------
__device__ float g_a   [(size_t)NB * NEMB];
__device__ float g_ar  [(size_t)NB * NEMB];
__device__ float g_b   [(size_t)NB * NEMB];
__device__ float g_br  [(size_t)NB * NEMB];
__device__ float g_z   [(size_t)NB * NEMB];
__device__ float g_cnorm[NK];
__device__ int   g_idx[NFLAT];
__device__ int   g_cnt[NK];
__device__ float g_losspart[NFLAT / 8];

// ---------------- small helpers ----------------
__device__ __forceinline__ uint32_t rtf32_u(float x) {
    uint32_t r;
    asm("cvt.rna.tf32.f32 %0, %1;" : "=r"(r) : "f"(x));
    return r;
}
__device__ __forceinline__ float rtf32(float x) {
    return __uint_as_float(rtf32_u(x));
}
__device__ __forceinline__ void cp16(uint32_t dst, const void* src) {
    asm volatile("cp.async.cg.shared.global [%0], [%1], 16;" :: "r"(dst), "l"(src));
}
__device__ __forceinline__ void cp_commit() {
    asm volatile("cp.async.commit_group;");
}
template<int N>
__device__ __forceinline__ void cp_wait() {
    asm volatile("cp.async.wait_group %0;" :: "n"(N));
}
__device__ __forceinline__ void mma8(float* c, const uint32_t* a, const uint32_t* b) {
    asm volatile(
        "mma.sync.aligned.m16n8k8.row.col.f32.tf32.tf32.f32 "
        "{%0,%1,%2,%3},{%4,%5,%6,%7},{%8,%9},{%0,%1,%2,%3};"
        : "+f"(c[0]), "+f"(c[1]), "+f"(c[2]), "+f"(c[3])
        : "r"(a[0]), "r"(a[1]), "r"(a[2]), "r"(a[3]), "r"(b[0]), "r"(b[1]));
}

// ---------------- tf32 tensor-core GEMM ----------------
// block tile 128x256, BK=32, 8 warps (2x4), warp tile 64x64, m16n8k8.
// operands converted to tf32 (rna) at fragment load -> no rounding pre-pass.
#define TBM 128
#define TBN 256
#define TBK 32
#define A_STR 36                         // BK + 4 pad (floats)
#define AS_SZ (TBM * A_STR)              // 4608 floats / stage
#define BS_SZ (TBK * TBN)                // 8192 floats / stage
#define GEMM_SMEM ((2 * AS_SZ + 2 * BS_SZ) * 4)

template<int EPI, bool WRELU>
__global__ void __launch_bounds__(256, 1)
gemm_tc(const float* __restrict__ A, const float* __restrict__ W,
        const float* __restrict__ bias,
        const float* __restrict__ gamma, const float* __restrict__ beta,
        const float* __restrict__ mean,  const float* __restrict__ var,
        const float* __restrict__ res,
        float* __restrict__ out0, float* __restrict__ out1,
        int M, int N, int K)
{
    extern __shared__ float smem[];
    float* As = smem;                    // 2 stages
    float* Bs = smem + 2 * AS_SZ;
    const uint32_t s_as = (uint32_t)__cvta_generic_to_shared(As);
    const uint32_t s_bs = (uint32_t)__cvta_generic_to_shared(Bs);

    const int tid  = threadIdx.x;
    const int lane = tid & 31;
    const int warp = tid >> 5;
    const int wm   = warp >> 2;          // 0..1
    const int wn   = warp & 3;           // 0..3
    const int row0 = blockIdx.y * TBM;
    const int col0 = blockIdx.x * TBN;
    const int l4   = lane >> 2;          // group id 0..7
    const int lm   = lane & 3;           // 0..3

    float acc[4][8][4];
#pragma unroll
    for (int mt = 0; mt < 4; mt++)
#pragma unroll
        for (int nt = 0; nt < 8; nt++)
#pragma unroll
            for (int q = 0; q < 4; q++) acc[mt][nt][q] = 0.f;

    const int iters = K / TBK;

    auto loadA = [&](int s, int k0) {
#pragma unroll
        for (int i = 0; i < 4; i++) {
            int idx = i * 256 + tid;
            int r = idx >> 3, kc = (idx & 7) << 2;
            cp16(s_as + (uint32_t)(s * AS_SZ + r * A_STR + kc) * 4,
                 A + (size_t)(row0 + r) * K + k0 + kc);
        }
    };
    auto loadB = [&](int s, int k0) {
#pragma unroll
        for (int i = 0; i < 8; i++) {
            int idx = i * 256 + tid;
            int k = idx >> 6, nc = (idx & 63) << 2;
            int nsw = nc ^ ((k & 3) << 3);
            cp16(s_bs + (uint32_t)(s * BS_SZ + k * TBN + nsw) * 4,
                 W + (size_t)(k0 + k) * N + col0 + nc);
        }
    };

    loadA(0, 0); loadB(0, 0); cp_commit();

    int s = 0;
    for (int it = 0; it < iters; it++) {
        if (it + 1 < iters) {
            loadA(s ^ 1, (it + 1) * TBK);
            loadB(s ^ 1, (it + 1) * TBK);
            cp_commit();
            cp_wait<1>();
        } else {
            cp_wait<0>();
        }
        __syncthreads();

        const float* as = As + s * AS_SZ;
        const float* bs = Bs + s * BS_SZ;
#pragma unroll
        for (int kk = 0; kk < TBK; kk += 8) {
            uint32_t af[4][4], bf[8][2];
#pragma unroll
            for (int mt = 0; mt < 4; mt++) {
                int r = wm * 64 + mt * 16 + l4;
                af[mt][0] = rtf32_u(as[r * A_STR + kk + lm]);
                af[mt][1] = rtf32_u(as[(r + 8) * A_STR + kk + lm]);
                af[mt][2] = rtf32_u(as[r * A_STR + kk + 4 + lm]);
                af[mt][3] = rtf32_u(as[(r + 8) * A_STR + kk + 4 + lm]);
            }
#pragma unroll
            for (int nt = 0; nt < 8; nt++) {
                int c   = wn * 64 + nt * 8 + l4;
                int csw = c ^ (lm << 3);
                bf[nt][0] = rtf32_u(bs[(kk + lm) * TBN + csw]);
                bf[nt][1] = rtf32_u(bs[(kk + 4 + lm) * TBN + csw]);
            }
#pragma unroll
            for (int mt = 0; mt < 4; mt++)
#pragma unroll
                for (int nt = 0; nt < 8; nt++)
                    mma8(acc[mt][nt], af[mt], bf[nt]);
        }
        __syncthreads();
        s ^= 1;
    }

    // ---- epilogue ----
#pragma unroll
    for (int nt = 0; nt < 8; nt++) {
        int c = col0 + wn * 64 + nt * 8 + (lm << 1);
        float b0 = bias[c], b1 = bias[c + 1];
        float g0 = 0.f, g1 = 0.f, be0 = 0.f, be1 = 0.f, m0 = 0.f, m1 = 0.f;
        if (EPI == EPI_BN_RELU || EPI == EPI_RES) {
            g0 = gamma[c]     * rsqrtf(var[c]     + 1e-5f);
            g1 = gamma[c + 1] * rsqrtf(var[c + 1] + 1e-5f);
            be0 = beta[c]; be1 = beta[c + 1];
            m0 = mean[c]; m1 = mean[c + 1];
        }
#pragma unroll
        for (int mt = 0; mt < 4; mt++) {
#pragma unroll
            for (int h = 0; h < 2; h++) {
                int r = row0 + wm * 64 + mt * 16 + l4 + h * 8;
                size_t off = (size_t)r * N + c;
                float x0 = acc[mt][nt][h * 2 + 0] + b0;
                float x1 = acc[mt][nt][h * 2 + 1] + b1;
                if (EPI == EPI_BN_RELU) {
                    x0 = fmaxf((x0 - m0) * g0 + be0, 0.f);
                    x1 = fmaxf((x1 - m1) * g1 + be1, 0.f);
                } else if (EPI == EPI_RES) {
                    float2 rv = *(const float2*)(res + off);
                    x0 = (x0 - m0) * g0 + be0 + rv.x;
                    x1 = (x1 - m1) * g1 + be1 + rv.y;
                } else if (EPI == EPI_SIG) {
                    // final output: full fp32, scalar stores (base unaligned)
                    out0[off]     = 1.f / (1.f + expf(-x0));
                    out0[off + 1] = 1.f / (1.f + expf(-x1));
                    continue;
                }
                float r0 = rtf32(x0), r1 = rtf32(x1);
                float2 v; v.x = r0; v.y = r1;
                *(float2*)(out0 + off) = v;
                if (WRELU) {
                    float2 w; w.x = fmaxf(r0, 0.f); w.y = fmaxf(r1, 0.f);
                    *(float2*)(out1 + off) = w;
                }
            }
        }
    }
}

// ---------------- VQ: tf32 mma distances + fused argmin ----------------
#define VB_STR 36
#define VBS_SZ (256 * VB_STR)
#define VQ_SMEM ((2 * AS_SZ + 2 * VBS_SZ) * 4)

__global__ void __launch_bounds__(256, 1)
vq_tc(const float* __restrict__ Z, const float* __restrict__ CB)
{
    extern __shared__ float smem[];
    float* As = smem;
    float* Bs = smem + 2 * AS_SZ;
    const uint32_t s_as = (uint32_t)__cvta_generic_to_shared(As);
    const uint32_t s_bs = (uint32_t)__cvta_generic_to_shared(Bs);
    __shared__ float sv[128][4];
    __shared__ int   si[128][4];

    const int tid  = threadIdx.x;
    const int lane = tid & 31;
    const int warp = tid >> 5;
    const int wm   = warp >> 2;
    const int wn   = warp & 3;
    const int row0 = blockIdx.x * 128;
    const int l4   = lane >> 2;
    const int lm   = lane & 3;

    float minv[4][2];
    int   mini[4][2];
#pragma unroll
    for (int mt = 0; mt < 4; mt++)
#pragma unroll
        for (int h = 0; h < 2; h++) { minv[mt][h] = 3.4e38f; mini[mt][h] = 0; }

    auto loadA = [&](int s, int k0) {
#pragma unroll
        for (int i = 0; i < 4; i++) {
            int idx = i * 256 + tid;
            int r = idx >> 3, kc = (idx & 7) << 2;
            cp16(s_as + (uint32_t)(s * AS_SZ + r * A_STR + kc) * 4,
                 Z + (size_t)(row0 + r) * NCD + k0 + kc);
        }
    };

    for (int ct = 0; ct < NK; ct += 256) {
        float acc[4][8][4];
#pragma unroll
        for (int mt = 0; mt < 4; mt++)
#pragma unroll
            for (int nt = 0; nt < 8; nt++)
#pragma unroll
                for (int q = 0; q < 4; q++) acc[mt][nt][q] = 0.f;

        auto loadB = [&](int s, int k0) {
#pragma unroll
            for (int i = 0; i < 8; i++) {
                int idx = i * 256 + tid;
                int code = idx >> 3, kc = (idx & 7) << 2;
                cp16(s_bs + (uint32_t)(s * VBS_SZ + code * VB_STR + kc) * 4,
                     CB + (size_t)(ct + code) * NCD + k0 + kc);
            }
        };

        loadA(0, 0); loadB(0, 0); cp_commit();
        int s = 0;
        const int iters = NCD / TBK;      // 8
        for (int it = 0; it < iters; it++) {
            if (it + 1 < iters) {
                loadA(s ^ 1, (it + 1) * TBK);
                loadB(s ^ 1, (it + 1) * TBK);
                cp_commit();
                cp_wait<1>();
            } else {
                cp_wait<0>();
            }
            __syncthreads();

            const float* as = As + s * AS_SZ;
            const float* bs = Bs + s * VBS_SZ;
#pragma unroll
            for (int kk = 0; kk < TBK; kk += 8) {
                uint32_t af[4][4], bf[8][2];
#pragma unroll
                for (int mt = 0; mt < 4; mt++) {
                    int r = wm * 64 + mt * 16 + l4;
                    af[mt][0] = rtf32_u(as[r * A_STR + kk + lm]);
                    af[mt][1] = rtf32_u(as[(r + 8) * A_STR + kk + lm]);
                    af[mt][2] = rtf32_u(as[r * A_STR + kk + 4 + lm]);
                    af[mt][3] = rtf32_u(as[(r + 8) * A_STR + kk + 4 + lm]);
                }
#pragma unroll
                for (int nt = 0; nt < 8; nt++) {
                    int cc = wn * 64 + nt * 8 + l4;
                    bf[nt][0] = rtf32_u(bs[cc * VB_STR + kk + lm]);
                    bf[nt][1] = rtf32_u(bs[cc * VB_STR + kk + 4 + lm]);
                }
#pragma unroll
                for (int mt = 0; mt < 4; mt++)
#pragma unroll
                    for (int nt = 0; nt < 8; nt++)
                        mma8(acc[mt][nt], af[mt], bf[nt]);
            }
            __syncthreads();
            s ^= 1;
        }

        // update running per-row argmin:  d = |c|^2 - 2 z.c
#pragma unroll
        for (int nt = 0; nt < 8; nt++) {
            int code = ct + wn * 64 + nt * 8 + (lm << 1);
            float cn0 = g_cnorm[code], cn1 = g_cnorm[code + 1];
#pragma unroll
            for (int mt = 0; mt < 4; mt++)
#pragma unroll
                for (int h = 0; h < 2; h++) {
                    float d0 = cn0 - 2.f * acc[mt][nt][h * 2 + 0];
                    float d1 = cn1 - 2.f * acc[mt][nt][h * 2 + 1];
                    if (d0 < minv[mt][h]) { minv[mt][h] = d0; mini[mt][h] = code; }
                    if (d1 < minv[mt][h]) { minv[mt][h] = d1; mini[mt][h] = code + 1; }
                }
        }
    }

    // reduce across the 4 lanes of each quad (they share rows, hold diff cols)
#pragma unroll
    for (int mt = 0; mt < 4; mt++)
#pragma unroll
        for (int h = 0; h < 2; h++) {
            float v = minv[mt][h]; int ix = mini[mt][h];
#pragma unroll
            for (int o = 1; o <= 2; o <<= 1) {
                float vo = __shfl_xor_sync(0xffffffffu, v, o);
                int   io = __shfl_xor_sync(0xffffffffu, ix, o);
                if (vo < v || (vo == v && io < ix)) { v = vo; ix = io; }
            }
            if (lm == 0) {
                int rl = wm * 64 + mt * 16 + l4 + h * 8;
                sv[rl][wn] = v; si[rl][wn] = ix;
            }
        }
    __syncthreads();
    if (tid < 128) {
        float bv = sv[tid][0]; int bi = si[tid][0];
#pragma unroll
        for (int t = 1; t < 4; t++) {
            float v = sv[tid][t]; int k2 = si[tid][t];
            if (v < bv || (v == bv && k2 < bi)) { bv = v; bi = k2; }
        }
        g_idx[row0 + tid] = bi;
        atomicAdd(&g_cnt[bi], 1);
    }
}

// ---------------- misc kernels ----------------
__global__ void zero_cnt_kernel()
{
    int i = blockIdx.x * 256 + threadIdx.x;
    if (i < NK) g_cnt[i] = 0;
}

__global__ __launch_bounds__(256)
void cnorm_kernel(const float* __restrict__ CB)
{
    int warp = threadIdx.x >> 5, lane = threadIdx.x & 31;
    int code = blockIdx.x * 8 + warp;
    const float* c = CB + (size_t)code * NCD;
    float s = 0.f;
#pragma unroll
    for (int e = 0; e < 8; e++) { float v = rtf32(c[e * 32 + lane]); s += v * v; }
#pragma unroll
    for (int o = 16; o > 0; o >>= 1) s += __shfl_xor_sync(0xffffffffu, s, o);
    if (lane == 0) g_cnorm[code] = s;
}

__global__ __launch_bounds__(256)
void gather_loss_kernel(const float* __restrict__ Z, const float* __restrict__ CB,
                        float* __restrict__ HQ, float* __restrict__ HQR)
{
    __shared__ float ws[8];
    int warp = threadIdx.x >> 5, lane = threadIdx.x & 31;
    int row  = blockIdx.x * 8 + warp;
    int id   = g_idx[row];
    const float* q = CB + (size_t)id * NCD;
    const float* z = Z + (size_t)row * NCD;
    float* o   = HQ  + (size_t)row * NCD;
    float* orl = HQR + (size_t)row * NCD;
    float s = 0.f;
#pragma unroll
    for (int e = 0; e < 8; e++) {
        int d = e * 32 + lane;
        float qq = q[d], zz = z[d];
        float qr = rtf32(qq);
        o[d]   = qr;
        orl[d] = fmaxf(qr, 0.f);
        float t = qq - zz;
        s += t * t;
    }
#pragma unroll
    for (int off = 16; off > 0; off >>= 1) s += __shfl_xor_sync(0xffffffffu, s, off);
    if (lane == 0) ws[warp] = s;
    __syncthreads();
    if (threadIdx.x == 0) {
        float t = 0.f;
#pragma unroll
        for (int w = 0; w < 8; w++) t += ws[w];
        g_losspart[blockIdx.x] = t;
    }
}

__global__ __launch_bounds__(256)
void finalize_kernel(float* __restrict__ out)
{
    __shared__ float red[256];
    int tid = threadIdx.x;

    float s = 0.f;
    for (int i = tid; i < NFLAT / 8; i += 256) s += g_losspart[i];
    red[tid] = s; __syncthreads();
    for (int o = 128; o > 0; o >>= 1) { if (tid < o) red[tid] += red[tid + o]; __syncthreads(); }
    float loss = red[0] * (1.25f / ((float)NB * (float)NEMB));
    __syncthreads();

    float e = 0.f;
    for (int i = tid; i < NK; i += 256) {
        float p = (float)g_cnt[i] * (1.0f / (float)NFLAT);
        e += p * logf(p + 1e-10f);
    }
    red[tid] = e; __syncthreads();
    for (int o = 128; o > 0; o >>= 1) { if (tid < o) red[tid] += red[tid + o]; __syncthreads(); }

    if (tid == 0) {
        out[0]            = loss;
        out[OUT_PERP_OFF] = expf(-red[0]);
    }
}

// ---------------- launch ----------------
extern "C" void kernel_launch(void* const* d_in, const int* in_sizes, int n_in,
                              void* d_out, int out_size)
{
    const float* x    = (const float*)d_in[0];
    const float* W1   = (const float*)d_in[1];
    const float* b1   = (const float*)d_in[2];
    const float* bn1g = (const float*)d_in[3];
    const float* bn1b = (const float*)d_in[4];
    const float* bn1m = (const float*)d_in[5];
    const float* bn1v = (const float*)d_in[6];
    const float* W2   = (const float*)d_in[7];
    const float* b2   = (const float*)d_in[8];
    const float* rbW  = (const float*)d_in[9];
    const float* rbb  = (const float*)d_in[10];
    const float* rbg  = (const float*)d_in[11];
    const float* rbbe = (const float*)d_in[12];
    const float* rbm  = (const float*)d_in[13];
    const float* rbv  = (const float*)d_in[14];
    const float* cb   = (const float*)d_in[15];
    const float* decW = (const float*)d_in[16];
    const float* decb = (const float*)d_in[17];
    float* out = (float*)d_out;

    float *ga, *gar, *gb, *gbr, *gz;
    cudaGetSymbolAddress((void**)&ga,  g_a);
    cudaGetSymbolAddress((void**)&gar, g_ar);
    cudaGetSymbolAddress((void**)&gb,  g_b);
    cudaGetSymbolAddress((void**)&gbr, g_br);
    cudaGetSymbolAddress((void**)&gz,  g_z);

    // dynamic smem opt-in (idempotent)
    cudaFuncSetAttribute(gemm_tc<EPI_BN_RELU, false>, cudaFuncAttributeMaxDynamicSharedMemorySize, GEMM_SMEM);
    cudaFuncSetAttribute(gemm_tc<EPI_BIAS,    true >, cudaFuncAttributeMaxDynamicSharedMemorySize, GEMM_SMEM);
    cudaFuncSetAttribute(gemm_tc<EPI_RES,     true >, cudaFuncAttributeMaxDynamicSharedMemorySize, GEMM_SMEM);
    cudaFuncSetAttribute(gemm_tc<EPI_RES,     false>, cudaFuncAttributeMaxDynamicSharedMemorySize, GEMM_SMEM);
    cudaFuncSetAttribute(gemm_tc<EPI_SIG,     false>, cudaFuncAttributeMaxDynamicSharedMemorySize, GEMM_SMEM);
    cudaFuncSetAttribute(vq_tc, cudaFuncAttributeMaxDynamicSharedMemorySize, VQ_SMEM);

    const size_t WS = (size_t)NEMB * NEMB;

    zero_cnt_kernel<<<(NK + 255) / 256, 256>>>();
    cnorm_kernel<<<NK / 8, 256>>>(cb);

    dim3 blk(256);
    dim3 gE(NEMB / TBN, NB / TBM);   // 4 x 32
    dim3 gD(NIN  / TBN, NB / TBM);   // 32 x 32

    // encoder (operands tf32-rounded inside the kernels)
    gemm_tc<EPI_BN_RELU, false><<<gE, blk, GEMM_SMEM>>>(
        x, W1, b1, bn1g, bn1b, bn1m, bn1v, nullptr, gar, nullptr, NB, NEMB, NIN);
    gemm_tc<EPI_BIAS, true><<<gE, blk, GEMM_SMEM>>>(
        gar, W2, b2, nullptr, nullptr, nullptr, nullptr, nullptr, gb, gbr, NB, NEMB, NEMB);
    gemm_tc<EPI_RES, true><<<gE, blk, GEMM_SMEM>>>(
        gbr, rbW + 0 * WS, rbb + 0 * NEMB, rbg + 0 * NEMB, rbbe + 0 * NEMB,
        rbm + 0 * NEMB, rbv + 0 * NEMB, gb, ga, gar, NB, NEMB, NEMB);
    gemm_tc<EPI_RES, false><<<gE, blk, GEMM_SMEM>>>(
        gar, rbW + 1 * WS, rbb + 1 * NEMB, rbg + 1 * NEMB, rbbe + 1 * NEMB,
        rbm + 1 * NEMB, rbv + 1 * NEMB, ga, gz, nullptr, NB, NEMB, NEMB);

    // vector quantizer
    vq_tc<<<NFLAT / 128, blk, VQ_SMEM>>>(gz, cb);
    gather_loss_kernel<<<NFLAT / 8, 256>>>(gz, cb, gb, gbr);
    finalize_kernel<<<1, 256>>>(out);

    // decoder
    gemm_tc<EPI_RES, true><<<gE, blk, GEMM_SMEM>>>(
        gbr, rbW + 2 * WS, rbb + 2 * NEMB, rbg + 2 * NEMB, rbbe + 2 * NEMB,
        rbm + 2 * NEMB, rbv + 2 * NEMB, gb, ga, gar, NB, NEMB, NEMB);
    gemm_tc<EPI_RES, true><<<gE, blk, GEMM_SMEM>>>(
        gar, rbW + 3 * WS, rbb + 3 * NEMB, rbg + 3 * NEMB, rbbe + 3 * NEMB,
        rbm + 3 * NEMB, rbv + 3 * NEMB, ga, gb, gbr, NB, NEMB, NEMB);
    gemm_tc<EPI_RES, false><<<gE, blk, GEMM_SMEM>>>(
        gbr, rbW + 4 * WS, rbb + 4 * NEMB, rbg + 4 * NEMB, rbbe + 4 * NEMB,
        rbm + 4 * NEMB, rbv + 4 * NEMB, gb, ga, nullptr, NB, NEMB, NEMB);

    gemm_tc<EPI_SIG, false><<<gD, blk, GEMM_SMEM>>>(
        ga, decW, decb, nullptr, nullptr, nullptr, nullptr, nullptr,
        out + 1, nullptr, NB, NIN, NEMB);
}